// round 6
// baseline (speedup 1.0000x reference)
#include <cuda_runtime.h>
#include <cuda_bf16.h>
#include <math.h>
#include <cstdint>

// ---------------- problem constants ----------------------------------------
constexpr int B   = 8;
constexpr int F   = 8;
constexpr int NS  = 196;
constexpr int NT  = 1 + F*NS;   // 1569
constexpr int D   = 768;
constexpr int H   = 12;
constexpr int HD  = 64;
constexpr int D3  = 3*D;        // 2304
constexpr int D4  = 4*D;        // 3072
constexpr int M   = B*NT;       // 12552
constexpr int MP  = 12672;      // M padded to 128
constexpr float LN_EPS = 1e-5f;
constexpr float QSCALE = 0.125f;

// ---------------- scratch (device globals; no allocation) ------------------
__device__ int8_t g_lnq1 [(size_t)M * D],  g_lnq2 [(size_t)M * D];
__device__ float  g_lns  [6 * MP];
__device__ float  g_qkv  [(size_t)M * D3];
__device__ float  g_att  [(size_t)M * D];
__device__ int8_t g_attq1[(size_t)M * D],  g_attq2[(size_t)M * D];
__device__ float  g_atts [6 * MP];
__device__ float  g_tres [(size_t)M * D];
__device__ float  g_sres [(size_t)M * D];
__device__ float  g_hid  [(size_t)M * D4];
__device__ int8_t g_hidq1[(size_t)M * D4], g_hidq2[(size_t)M * D4];
__device__ float  g_hids [24 * MP];
__device__ float  g_wtmp [(size_t)3072 * 768];
// quantized transposed weights: Wt[n][k]
__device__ int8_t g_q1_tqkv [(size_t)D3*D], g_q2_tqkv [(size_t)D3*D];  __device__ float g_s_tqkv [6*D3];
__device__ int8_t g_q1_aqkv [(size_t)D3*D], g_q2_aqkv [(size_t)D3*D];  __device__ float g_s_aqkv [6*D3];
__device__ int8_t g_q1_tproj[(size_t)D*D],  g_q2_tproj[(size_t)D*D];   __device__ float g_s_tproj[6*D];
__device__ int8_t g_q1_aproj[(size_t)D*D],  g_q2_aproj[(size_t)D*D];   __device__ float g_s_aproj[6*D];
__device__ int8_t g_q1_fc1  [(size_t)D4*D], g_q2_fc1  [(size_t)D4*D];  __device__ float g_s_fc1  [6*D4];
__device__ int8_t g_q1_fc2  [(size_t)D*D4], g_q2_fc2  [(size_t)D*D4];  __device__ float g_s_fc2  [24*D];

// ---------------- helpers ----------------------------------------------------
__device__ __forceinline__ uint32_t smem_to_u32(const void* p) {
    uint32_t a;
    asm("{ .reg .u64 t; cvta.to.shared.u64 t, %1; cvt.u32.u64 %0, t; }"
        : "=r"(a) : "l"(p));
    return a;
}
__device__ __forceinline__ void cp_async16(uint32_t dst, const void* src, bool valid) {
    int sz = valid ? 16 : 0;
    asm volatile("cp.async.cg.shared.global [%0], [%1], 16, %2;"
                 :: "r"(dst), "l"(src), "r"(sz) : "memory");
}
#define CP_COMMIT()  asm volatile("cp.async.commit_group;" ::: "memory")
#define CP_WAIT(n)   asm volatile("cp.async.wait_group %0;" :: "n"(n) : "memory")

__device__ __forceinline__ void ldsm_x4(uint32_t& r0, uint32_t& r1, uint32_t& r2, uint32_t& r3, uint32_t addr) {
    asm volatile("ldmatrix.sync.aligned.m8n8.x4.shared.b16 {%0,%1,%2,%3}, [%4];"
                 : "=r"(r0), "=r"(r1), "=r"(r2), "=r"(r3) : "r"(addr));
}
__device__ __forceinline__ void mma_s8(int* c, const uint32_t* a, const uint32_t* b) {
    asm volatile(
        "mma.sync.aligned.m16n8k32.row.col.s32.s8.s8.s32 "
        "{%0,%1,%2,%3}, {%4,%5,%6,%7}, {%8,%9}, {%0,%1,%2,%3};"
        : "+r"(c[0]), "+r"(c[1]), "+r"(c[2]), "+r"(c[3])
        : "r"(a[0]), "r"(a[1]), "r"(a[2]), "r"(a[3]), "r"(b[0]), "r"(b[1]));
}
__device__ __forceinline__ float gelu_exact(float v) {
    return 0.5f * v * (1.f + erff(v * 0.70710678118654752f));
}

// ---------------- int8x2 GEMM --------------------------------------------------
// C[M][N] = A[M][K] @ Wt[N][K]^T, both sides quantized per (row, 128-K-block):
// x ~= s * (x1 + x2/128).  Per chunk: main = a1b1, cross = a1b2 + a2b1.
// C += float(main*128 + cross) * sA * sB'   (sB' has the /128 folded in)
constexpr int BM = 128, BN = 128, BK = 128;
constexpr int RSB = 144;                  // 128B data + 16B pad
constexpr int MAT_B = 128 * RSB;          // 18432
constexpr int SC_OFF = 4 * MAT_B;         // scales after 4 matrices
constexpr int STAGE_B = 4*MAT_B + 1024;   // + sA(512) + sB(512) = 74752
constexpr int SMEM_GEMM = 2 * STAGE_B;    // 149504

// EPI: 0 = bias, 1 = bias+residual, 2 = bias+GELU
template<int EPI>
__global__ void __launch_bounds__(256, 1)
gemm_s8(const int8_t* __restrict__ Aq1, const int8_t* __restrict__ Aq2,
        const float* __restrict__ As, int AsStride,
        const int8_t* __restrict__ Bq1, const int8_t* __restrict__ Bq2,
        const float* __restrict__ Bs,
        const float* __restrict__ bias, const float* __restrict__ R,
        float* __restrict__ C, int Mr, int K, int Nc)
{
    extern __shared__ char smem[];
    const uint32_t sb = smem_to_u32(smem);
    const int tid = threadIdx.x;
    const int wid = tid >> 5, lane = tid & 31;
    const int wm = wid & 1, wn = wid >> 1;          // warp tile (wm*64, wn*32)
    const int bm = blockIdx.y * BM, bn = blockIdx.x * BN;

    float acc[4][4][4];
    #pragma unroll
    for (int i = 0; i < 4; i++)
        #pragma unroll
        for (int j = 0; j < 4; j++)
            #pragma unroll
            for (int q = 0; q < 4; q++) acc[i][j][q] = 0.f;

    auto load_stage = [&](int stage, int c) {
        uint32_t base = sb + stage * STAGE_B;
        int k0 = c * BK;
        #pragma unroll
        for (int i = 0; i < 4; i++) {                 // A1, A2
            int idx = tid + i*256;
            int r = idx >> 3, cb = (idx & 7) << 4;
            int gr = bm + r;
            bool v = gr < Mr;
            cp_async16(base + 0*MAT_B + r*RSB + cb, Aq1 + (size_t)(v?gr:0)*K + k0 + cb, v);
            cp_async16(base + 1*MAT_B + r*RSB + cb, Aq2 + (size_t)(v?gr:0)*K + k0 + cb, v);
        }
        #pragma unroll
        for (int i = 0; i < 4; i++) {                 // B1, B2
            int idx = tid + i*256;
            int r = idx >> 3, cb = (idx & 7) << 4;
            cp_async16(base + 2*MAT_B + r*RSB + cb, Bq1 + (size_t)(bn + r)*K + k0 + cb, true);
            cp_async16(base + 3*MAT_B + r*RSB + cb, Bq2 + (size_t)(bn + r)*K + k0 + cb, true);
        }
        if (tid < 32)                                  // sA: 128 floats
            cp_async16(base + SC_OFF + tid*16, As + (size_t)c*AsStride + bm + tid*4, true);
        else if (tid < 64)                             // sB: 128 floats
            cp_async16(base + SC_OFF + 512 + (tid-32)*16, Bs + (size_t)c*Nc + bn + (tid-32)*4, true);
        CP_COMMIT();
    };

    const int NC = K / BK;
    load_stage(0, 0);

    const int aRow = (lane & 15);
    const int aColB = (lane >> 4) * 16;
    const int bMtx = lane >> 3, bRit = lane & 7;
    const int bNrow = (bMtx & 2) ? (8 + bRit) : bRit;
    const int bKoff = (bMtx & 1) * 16;
    const int er = lane >> 2, ec = (lane & 3) * 2;

    for (int c = 0; c < NC; c++) {
        if (c + 1 < NC) { load_stage((c + 1) & 1, c + 1); CP_WAIT(1); }
        else            { CP_WAIT(0); }
        __syncthreads();

        uint32_t st = sb + (c & 1) * STAGE_B;
        uint32_t a1b = st, a2b = st + MAT_B, b1b = st + 2*MAT_B, b2b = st + 3*MAT_B;
        uint32_t sAb = st + SC_OFF, sBb = st + SC_OFF + 512;

        #pragma unroll
        for (int half = 0; half < 2; half++) {
            int accM[8][4], accC[8][4];
            #pragma unroll
            for (int t = 0; t < 8; t++)
                #pragma unroll
                for (int q = 0; q < 4; q++) { accM[t][q] = 0; accC[t][q] = 0; }

            #pragma unroll
            for (int kk = 0; kk < 4; kk++) {
                uint32_t a1[4][4], a2[4][4], b1[2][2], b2[2][2];
                #pragma unroll
                for (int mt = 0; mt < 4; mt++) {
                    uint32_t off = (uint32_t)((wm*64 + mt*16 + aRow) * RSB + kk*32 + aColB);
                    ldsm_x4(a1[mt][0], a1[mt][1], a1[mt][2], a1[mt][3], a1b + off);
                    ldsm_x4(a2[mt][0], a2[mt][1], a2[mt][2], a2[mt][3], a2b + off);
                }
                {
                    uint32_t off = (uint32_t)((wn*32 + half*16 + bNrow) * RSB + kk*32 + bKoff);
                    ldsm_x4(b1[0][0], b1[0][1], b1[1][0], b1[1][1], b1b + off);
                    ldsm_x4(b2[0][0], b2[0][1], b2[1][0], b2[1][1], b2b + off);
                }
                #pragma unroll
                for (int mt = 0; mt < 4; mt++)
                    #pragma unroll
                    for (int n2 = 0; n2 < 2; n2++)
                        mma_s8(accM[mt*2+n2], a1[mt], b1[n2]);
                #pragma unroll
                for (int mt = 0; mt < 4; mt++)
                    #pragma unroll
                    for (int n2 = 0; n2 < 2; n2++)
                        mma_s8(accC[mt*2+n2], a1[mt], b2[n2]);
                #pragma unroll
                for (int mt = 0; mt < 4; mt++)
                    #pragma unroll
                    for (int n2 = 0; n2 < 2; n2++)
                        mma_s8(accC[mt*2+n2], a2[mt], b1[n2]);
            }

            // dequant into fp32 accumulators
            #pragma unroll
            for (int mt = 0; mt < 4; mt++) {
                float sa0, sa1;
                asm volatile("ld.shared.f32 %0, [%1];" : "=f"(sa0)
                             : "r"(sAb + (uint32_t)((wm*64 + mt*16 + er) * 4)));
                asm volatile("ld.shared.f32 %0, [%1];" : "=f"(sa1)
                             : "r"(sAb + (uint32_t)((wm*64 + mt*16 + er + 8) * 4)));
                #pragma unroll
                for (int n2 = 0; n2 < 2; n2++) {
                    float sb0, sb1;
                    uint32_t co = sBb + (uint32_t)((wn*32 + half*16 + n2*8 + ec) * 4);
                    asm volatile("ld.shared.f32 %0, [%1];" : "=f"(sb0) : "r"(co));
                    asm volatile("ld.shared.f32 %0, [%1];" : "=f"(sb1) : "r"(co + 4));
                    int t = mt*2 + n2, nt = half*2 + n2;
                    acc[mt][nt][0] += (float)(accM[t][0]*128 + accC[t][0]) * (sa0*sb0);
                    acc[mt][nt][1] += (float)(accM[t][1]*128 + accC[t][1]) * (sa0*sb1);
                    acc[mt][nt][2] += (float)(accM[t][2]*128 + accC[t][2]) * (sa1*sb0);
                    acc[mt][nt][3] += (float)(accM[t][3]*128 + accC[t][3]) * (sa1*sb1);
                }
            }
        }
        __syncthreads();
    }

    #pragma unroll
    for (int mt = 0; mt < 4; mt++) {
        int r0 = bm + wm*64 + mt*16 + er;
        int r1 = r0 + 8;
        #pragma unroll
        for (int nt = 0; nt < 4; nt++) {
            int cc = bn + wn*32 + nt*8 + ec;
            float b0 = bias[cc], b1 = bias[cc + 1];
            if (r0 < Mr) {
                float v0 = acc[mt][nt][0] + b0;
                float v1 = acc[mt][nt][1] + b1;
                size_t off = (size_t)r0 * Nc + cc;
                if (EPI == 1) { v0 += R[off]; v1 += R[off + 1]; }
                if (EPI == 2) { v0 = gelu_exact(v0); v1 = gelu_exact(v1); }
                C[off] = v0; C[off + 1] = v1;
            }
            if (r1 < Mr) {
                float v2 = acc[mt][nt][2] + b0;
                float v3 = acc[mt][nt][3] + b1;
                size_t off = (size_t)r1 * Nc + cc;
                if (EPI == 1) { v2 += R[off]; v3 += R[off + 1]; }
                if (EPI == 2) { v2 = gelu_exact(v2); v3 = gelu_exact(v3); }
                C[off] = v2; C[off + 1] = v3;
            }
        }
    }
}

// ---------------- quantization helpers ----------------------------------------
__device__ __forceinline__ void quant_block_lane(const float* v4, float inv,
                                                 char4& c1, char4& c2)
{
    int a1[4], a2[4];
    #pragma unroll
    for (int j = 0; j < 4; j++) {
        float s = v4[j] * inv;
        a1[j] = (int)rintf(s);
        a2[j] = (int)rintf((s - (float)a1[j]) * 128.f);
    }
    c1 = make_char4((char)a1[0], (char)a1[1], (char)a1[2], (char)a1[3]);
    c2 = make_char4((char)a2[0], (char)a2[1], (char)a2[2], (char)a2[3]);
}

// generic row-block quantizer: X[rows][Kd] -> Q1,Q2 int8 + St[kb][srows]
__global__ void rowquant_kernel(const float* __restrict__ X,
                                int8_t* __restrict__ Q1, int8_t* __restrict__ Q2,
                                float* __restrict__ St,
                                int Kd, int srows, float postscale)
{
    int r = blockIdx.x;
    int w = threadIdx.x >> 5, lane = threadIdx.x & 31;
    const float* x = X + (size_t)r * Kd;
    for (int kb = w; kb < Kd/128; kb += 8) {
        float v[4]; float mx = 0.f;
        #pragma unroll
        for (int j = 0; j < 4; j++) {
            v[j] = x[kb*128 + lane*4 + j];
            mx = fmaxf(mx, fabsf(v[j]));
        }
        #pragma unroll
        for (int o = 16; o > 0; o >>= 1) mx = fmaxf(mx, __shfl_xor_sync(0xffffffffu, mx, o));
        float inv = mx > 0.f ? 127.f/mx : 0.f;
        char4 c1, c2;
        quant_block_lane(v, inv, c1, c2);
        size_t o = (size_t)r*Kd + kb*128 + lane*4;
        *(char4*)&Q1[o] = c1;
        *(char4*)&Q2[o] = c2;
        if (lane == 0) St[(size_t)kb*srows + r] = mx * postscale;
    }
}

// LayerNorm + quantize (D = 768 fixed, 6 blocks)
__global__ void ln_quant_kernel(const float* __restrict__ X,
                                const float* __restrict__ gam,
                                const float* __restrict__ bet,
                                int8_t* __restrict__ Q1, int8_t* __restrict__ Q2,
                                float* __restrict__ St)
{
    int row = blockIdx.x;
    const float* x = X + (size_t)row * D;
    int tid = threadIdx.x;
    __shared__ float vrow[D];

    float s = 0.f, ss = 0.f;
    for (int i = tid; i < D; i += 256) { float v = x[i]; s += v; ss += v*v; }
    __shared__ float rs[8], rss[8];
    #pragma unroll
    for (int o = 16; o > 0; o >>= 1) {
        s  += __shfl_xor_sync(0xffffffffu, s,  o);
        ss += __shfl_xor_sync(0xffffffffu, ss, o);
    }
    int w = tid >> 5, lane = tid & 31;
    if (lane == 0) { rs[w] = s; rss[w] = ss; }
    __syncthreads();
    __shared__ float s_mean, s_inv;
    if (tid == 0) {
        float ts = 0.f, tss = 0.f;
        for (int k = 0; k < 8; k++) { ts += rs[k]; tss += rss[k]; }
        float mean = ts * (1.f/D);
        float var  = tss * (1.f/D) - mean*mean;
        s_mean = mean; s_inv = rsqrtf(var + LN_EPS);
    }
    __syncthreads();
    float mean = s_mean, inv = s_inv;
    for (int i = tid; i < D; i += 256)
        vrow[i] = (x[i] - mean) * inv * gam[i] + bet[i];
    __syncthreads();

    if (w < 6) {
        float v[4]; float mx = 0.f;
        #pragma unroll
        for (int j = 0; j < 4; j++) {
            v[j] = vrow[w*128 + lane*4 + j];
            mx = fmaxf(mx, fabsf(v[j]));
        }
        #pragma unroll
        for (int o = 16; o > 0; o >>= 1) mx = fmaxf(mx, __shfl_xor_sync(0xffffffffu, mx, o));
        float qi = mx > 0.f ? 127.f/mx : 0.f;
        char4 c1, c2;
        quant_block_lane(v, qi, c1, c2);
        size_t o = (size_t)row*D + w*128 + lane*4;
        *(char4*)&Q1[o] = c1;
        *(char4*)&Q2[o] = c2;
        if (lane == 0) St[(size_t)w*MP + row] = mx * (1.f/127.f);
    }
}

// ---------------- weight transpose: W[K][N] -> Wt[N][K] fp32 -----------------
__global__ void wtrans_kernel(const float* __restrict__ W, float* __restrict__ Wt,
                              int K, int N)
{
    __shared__ float t[32][33];
    int n0 = blockIdx.x * 32, k0 = blockIdx.y * 32;
    int tx = threadIdx.x, ty = threadIdx.y;
    for (int i = ty; i < 32; i += 8)
        t[i][tx] = W[(size_t)(k0 + i) * N + n0 + tx];
    __syncthreads();
    for (int r = ty; r < 32; r += 8)
        Wt[(size_t)(n0 + r) * K + k0 + tx] = t[tx][r];
}

// ---------------- attention kernels (fp32) -----------------------------------
__global__ void attn_cls_kernel(const float* __restrict__ qkv,
                                float* __restrict__ att)
{
    int bh = blockIdx.x;
    int b = bh / H, hh = bh % H;
    int tid = threadIdx.x;

    __shared__ float qs[HD];
    __shared__ float sim[NT];
    __shared__ float red[256];
    __shared__ float red2[4][HD];

    if (tid < HD)
        qs[tid] = qkv[(size_t)(b*NT) * D3 + hh*HD + tid] * QSCALE;
    __syncthreads();

    float lmx = -1e30f;
    for (int j = tid; j < NT; j += 256) {
        const float* kp = qkv + (size_t)(b*NT + j) * D3 + D + hh*HD;
        float s = 0.f;
        #pragma unroll
        for (int d = 0; d < HD; d++) s += qs[d] * kp[d];
        sim[j] = s;
        lmx = fmaxf(lmx, s);
    }
    red[tid] = lmx; __syncthreads();
    for (int st = 128; st > 0; st >>= 1) {
        if (tid < st) red[tid] = fmaxf(red[tid], red[tid+st]);
        __syncthreads();
    }
    float mx = red[0];
    __syncthreads();

    float ls = 0.f;
    for (int j = tid; j < NT; j += 256) {
        float e = __expf(sim[j] - mx);
        sim[j] = e;
        ls += e;
    }
    red[tid] = ls; __syncthreads();
    for (int st = 128; st > 0; st >>= 1) {
        if (tid < st) red[tid] += red[tid+st];
        __syncthreads();
    }
    float linv = 1.f / red[0];
    __syncthreads();

    int d = tid & 63, p = tid >> 6;
    float acc = 0.f;
    for (int j = p; j < NT; j += 4)
        acc += sim[j] * qkv[(size_t)(b*NT + j) * D3 + 2*D + hh*HD + d];
    red2[p][d] = acc;
    __syncthreads();
    if (p == 0) {
        float o = (red2[0][d] + red2[1][d] + red2[2][d] + red2[3][d]) * linv;
        att[(size_t)(b*NT) * D + hh*HD + d] = o;
    }
}

__global__ void attn_time_kernel(const float* __restrict__ qkv,
                                 float* __restrict__ att)
{
    int qid = blockIdx.x * blockDim.x + threadIdx.x;
    int fr = qid % F;
    int sp = (qid / F) % NS;
    int bh = qid / (F * NS);
    int b = bh / H, hh = bh % H;
    int t = 1 + fr*NS + sp;

    const float4* qp = (const float4*)(qkv + (size_t)(b*NT + t) * D3 + hh*HD);
    float4 q4[16];
    #pragma unroll
    for (int i = 0; i < 16; i++) {
        float4 v = qp[i];
        v.x *= QSCALE; v.y *= QSCALE; v.z *= QSCALE; v.w *= QSCALE;
        q4[i] = v;
    }

    float sim[F+1];
    #pragma unroll
    for (int j = 0; j < F+1; j++) {
        int tk = (j == 0) ? 0 : (1 + (j-1)*NS + sp);
        const float4* kp = (const float4*)(qkv + (size_t)(b*NT + tk) * D3 + D + hh*HD);
        float s = 0.f;
        #pragma unroll
        for (int i = 0; i < 16; i++) {
            float4 kk = kp[i];
            s += q4[i].x*kk.x + q4[i].y*kk.y + q4[i].z*kk.z + q4[i].w*kk.w;
        }
        sim[j] = s;
    }
    float mx = sim[0];
    #pragma unroll
    for (int j = 1; j < F+1; j++) mx = fmaxf(mx, sim[j]);
    float l = 0.f;
    #pragma unroll
    for (int j = 0; j < F+1; j++) { sim[j] = __expf(sim[j] - mx); l += sim[j]; }
    float inv = 1.f / l;

    float4 o4[16];
    #pragma unroll
    for (int i = 0; i < 16; i++) o4[i] = make_float4(0.f,0.f,0.f,0.f);
    #pragma unroll
    for (int j = 0; j < F+1; j++) {
        int tk = (j == 0) ? 0 : (1 + (j-1)*NS + sp);
        const float4* vp = (const float4*)(qkv + (size_t)(b*NT + tk) * D3 + 2*D + hh*HD);
        float p = sim[j] * inv;
        #pragma unroll
        for (int i = 0; i < 16; i++) {
            float4 vv = vp[i];
            o4[i].x += p*vv.x; o4[i].y += p*vv.y; o4[i].z += p*vv.z; o4[i].w += p*vv.w;
        }
    }
    float4* op = (float4*)(att + (size_t)(b*NT + t) * D + hh*HD);
    #pragma unroll
    for (int i = 0; i < 16; i++) op[i] = o4[i];
}

__global__ void attn_space_kernel(const float* __restrict__ qkv,
                                  float* __restrict__ att)
{
    int bx = blockIdx.x;
    int bh = bx / F, fr = bx % F;
    int b = bh / H, hh = bh % H;
    int tid = threadIdx.x;
    int sp = tid;
    const int NK = NS + 1;

    __shared__ float Ks[64 * HD];
    __shared__ float Vs[64 * HD];

    float4 q4[16], o4[16];
    float m = -1e30f, l = 0.f;
    if (sp < NS) {
        const float4* qp = (const float4*)(qkv + (size_t)(b*NT + 1 + fr*NS + sp) * D3 + hh*HD);
        #pragma unroll
        for (int i = 0; i < 16; i++) {
            float4 v = qp[i];
            v.x *= QSCALE; v.y *= QSCALE; v.z *= QSCALE; v.w *= QSCALE;
            q4[i] = v;
            o4[i] = make_float4(0.f,0.f,0.f,0.f);
        }
    }

    for (int t0 = 0; t0 < NK; t0 += 64) {
        __syncthreads();
        for (int e = tid; e < 64*HD; e += 256) {
            int jj = e >> 6, d = e & 63;
            int j = t0 + jj;
            float kv = 0.f, vv = 0.f;
            if (j < NK) {
                int tk = (j == 0) ? 0 : (1 + fr*NS + (j-1));
                size_t base = (size_t)(b*NT + tk) * D3 + hh*HD + d;
                kv = qkv[base + D];
                vv = qkv[base + 2*D];
            }
            Ks[e] = kv; Vs[e] = vv;
        }
        __syncthreads();

        if (sp < NS) {
            int lim = min(64, NK - t0);
            for (int jj = 0; jj < lim; jj++) {
                const float4* kr = (const float4*)&Ks[jj * HD];
                float s = 0.f;
                #pragma unroll
                for (int i = 0; i < 16; i++) {
                    float4 kk = kr[i];
                    s += q4[i].x*kk.x + q4[i].y*kk.y + q4[i].z*kk.z + q4[i].w*kk.w;
                }
                float mn  = fmaxf(m, s);
                float fac = __expf(m - mn);
                float p   = __expf(s - mn);
                l = l * fac + p;
                const float4* vr = (const float4*)&Vs[jj * HD];
                #pragma unroll
                for (int i = 0; i < 16; i++) {
                    float4 vv = vr[i];
                    o4[i].x = o4[i].x*fac + p*vv.x;
                    o4[i].y = o4[i].y*fac + p*vv.y;
                    o4[i].z = o4[i].z*fac + p*vv.z;
                    o4[i].w = o4[i].w*fac + p*vv.w;
                }
                m = mn;
            }
        }
    }

    if (sp < NS) {
        float inv = 1.f / l;
        float4* op = (float4*)(att + (size_t)(b*NT + 1 + fr*NS + sp) * D + hh*HD);
        #pragma unroll
        for (int i = 0; i < 16; i++)
            op[i] = make_float4(o4[i].x*inv, o4[i].y*inv, o4[i].z*inv, o4[i].w*inv);
    }
}

// ---------------- host launch ------------------------------------------------
extern "C" void kernel_launch(void* const* d_in, const int* in_sizes, int n_in,
                              void* d_out, int out_size)
{
    const float* x      = (const float*)d_in[0];
    const float* n1g    = (const float*)d_in[1];
    const float* n1b    = (const float*)d_in[2];
    const float* n2g    = (const float*)d_in[3];
    const float* n2b    = (const float*)d_in[4];
    const float* n3g    = (const float*)d_in[5];
    const float* n3b    = (const float*)d_in[6];
    const float* aqkvw  = (const float*)d_in[7];
    const float* aqkvb  = (const float*)d_in[8];
    const float* aprojw = (const float*)d_in[9];
    const float* aprojb = (const float*)d_in[10];
    const float* tqkvw  = (const float*)d_in[11];
    const float* tqkvb  = (const float*)d_in[12];
    const float* tprojw = (const float*)d_in[13];
    const float* tprojb = (const float*)d_in[14];
    const float* fc1w   = (const float*)d_in[15];
    const float* fc1b   = (const float*)d_in[16];
    const float* fc2w   = (const float*)d_in[17];
    const float* fc2b   = (const float*)d_in[18];
    float* out = (float*)d_out;

    int8_t *lnq1,*lnq2,*attq1,*attq2,*hidq1,*hidq2;
    float *lns,*atts,*hids,*bqkv,*batt,*btres,*bsres,*bhid,*wtmp;
    cudaGetSymbolAddress((void**)&lnq1, g_lnq1);   cudaGetSymbolAddress((void**)&lnq2, g_lnq2);
    cudaGetSymbolAddress((void**)&lns,  g_lns);
    cudaGetSymbolAddress((void**)&attq1,g_attq1);  cudaGetSymbolAddress((void**)&attq2,g_attq2);
    cudaGetSymbolAddress((void**)&atts, g_atts);
    cudaGetSymbolAddress((void**)&hidq1,g_hidq1);  cudaGetSymbolAddress((void**)&hidq2,g_hidq2);
    cudaGetSymbolAddress((void**)&hids, g_hids);
    cudaGetSymbolAddress((void**)&bqkv, g_qkv);    cudaGetSymbolAddress((void**)&batt, g_att);
    cudaGetSymbolAddress((void**)&btres,g_tres);   cudaGetSymbolAddress((void**)&bsres,g_sres);
    cudaGetSymbolAddress((void**)&bhid, g_hid);    cudaGetSymbolAddress((void**)&wtmp, g_wtmp);

    int8_t *q1_tqkv,*q2_tqkv,*q1_aqkv,*q2_aqkv,*q1_tproj,*q2_tproj,*q1_aproj,*q2_aproj,*q1_fc1,*q2_fc1,*q1_fc2,*q2_fc2;
    float *s_tqkv,*s_aqkv,*s_tproj,*s_aproj,*s_fc1,*s_fc2;
    cudaGetSymbolAddress((void**)&q1_tqkv, g_q1_tqkv); cudaGetSymbolAddress((void**)&q2_tqkv, g_q2_tqkv);
    cudaGetSymbolAddress((void**)&s_tqkv, g_s_tqkv);
    cudaGetSymbolAddress((void**)&q1_aqkv, g_q1_aqkv); cudaGetSymbolAddress((void**)&q2_aqkv, g_q2_aqkv);
    cudaGetSymbolAddress((void**)&s_aqkv, g_s_aqkv);
    cudaGetSymbolAddress((void**)&q1_tproj,g_q1_tproj);cudaGetSymbolAddress((void**)&q2_tproj,g_q2_tproj);
    cudaGetSymbolAddress((void**)&s_tproj,g_s_tproj);
    cudaGetSymbolAddress((void**)&q1_aproj,g_q1_aproj);cudaGetSymbolAddress((void**)&q2_aproj,g_q2_aproj);
    cudaGetSymbolAddress((void**)&s_aproj,g_s_aproj);
    cudaGetSymbolAddress((void**)&q1_fc1, g_q1_fc1);   cudaGetSymbolAddress((void**)&q2_fc1, g_q2_fc1);
    cudaGetSymbolAddress((void**)&s_fc1, g_s_fc1);
    cudaGetSymbolAddress((void**)&q1_fc2, g_q1_fc2);   cudaGetSymbolAddress((void**)&q2_fc2, g_q2_fc2);
    cudaGetSymbolAddress((void**)&s_fc2, g_s_fc2);

    cudaFuncSetAttribute(gemm_s8<0>, cudaFuncAttributeMaxDynamicSharedMemorySize, SMEM_GEMM);
    cudaFuncSetAttribute(gemm_s8<1>, cudaFuncAttributeMaxDynamicSharedMemorySize, SMEM_GEMM);
    cudaFuncSetAttribute(gemm_s8<2>, cudaFuncAttributeMaxDynamicSharedMemorySize, SMEM_GEMM);

    const int MT = (M + BM - 1) / BM;    // 99
    dim3 tb(32, 8);
    const float wps = 1.f / (127.f * 128.f);   // weight postscale (folds /128)

    // ---- weight transpose + quantize ----
    wtrans_kernel<<<dim3(D3/32, D/32), tb>>>(tqkvw, wtmp, D, D3);
    rowquant_kernel<<<D3, 256>>>(wtmp, q1_tqkv, q2_tqkv, s_tqkv, D, D3, wps);
    wtrans_kernel<<<dim3(D3/32, D/32), tb>>>(aqkvw, wtmp, D, D3);
    rowquant_kernel<<<D3, 256>>>(wtmp, q1_aqkv, q2_aqkv, s_aqkv, D, D3, wps);
    wtrans_kernel<<<dim3(D/32, D/32), tb>>>(tprojw, wtmp, D, D);
    rowquant_kernel<<<D, 256>>>(wtmp, q1_tproj, q2_tproj, s_tproj, D, D, wps);
    wtrans_kernel<<<dim3(D/32, D/32), tb>>>(aprojw, wtmp, D, D);
    rowquant_kernel<<<D, 256>>>(wtmp, q1_aproj, q2_aproj, s_aproj, D, D, wps);
    wtrans_kernel<<<dim3(D4/32, D/32), tb>>>(fc1w, wtmp, D, D4);
    rowquant_kernel<<<D4, 256>>>(wtmp, q1_fc1, q2_fc1, s_fc1, D, D4, wps);
    wtrans_kernel<<<dim3(D/32, D4/32), tb>>>(fc2w, wtmp, D4, D);
    rowquant_kernel<<<D, 256>>>(wtmp, q1_fc2, q2_fc2, s_fc2, D4, D, wps);

    const int nTimeBlocks = (B*H*NS*F) / 256;   // 588

    // ---- time attention branch ----
    ln_quant_kernel<<<M, 256>>>(x, n3g, n3b, lnq1, lnq2, lns);
    gemm_s8<0><<<dim3(D3/BN, MT), 256, SMEM_GEMM>>>(lnq1, lnq2, lns, MP, q1_tqkv, q2_tqkv, s_tqkv, tqkvb, nullptr, bqkv, M, D, D3);
    attn_cls_kernel <<<B*H, 256>>>(bqkv, batt);
    attn_time_kernel<<<nTimeBlocks, 256>>>(bqkv, batt);
    rowquant_kernel<<<M, 256>>>(batt, attq1, attq2, atts, D, MP, 1.f/127.f);
    gemm_s8<1><<<dim3(D/BN, MT), 256, SMEM_GEMM>>>(attq1, attq2, atts, MP, q1_tproj, q2_tproj, s_tproj, tprojb, x, btres, M, D, D);

    // ---- space attention branch ----
    ln_quant_kernel<<<M, 256>>>(btres, n1g, n1b, lnq1, lnq2, lns);
    gemm_s8<0><<<dim3(D3/BN, MT), 256, SMEM_GEMM>>>(lnq1, lnq2, lns, MP, q1_aqkv, q2_aqkv, s_aqkv, aqkvb, nullptr, bqkv, M, D, D3);
    attn_cls_kernel  <<<B*H, 256>>>(bqkv, batt);
    attn_space_kernel<<<B*H*F, 256>>>(bqkv, batt);
    rowquant_kernel<<<M, 256>>>(batt, attq1, attq2, atts, D, MP, 1.f/127.f);
    gemm_s8<1><<<dim3(D/BN, MT), 256, SMEM_GEMM>>>(attq1, attq2, atts, MP, q1_aproj, q2_aproj, s_aproj, aprojb, x, bsres, M, D, D);

    // ---- MLP ----
    ln_quant_kernel<<<M, 256>>>(bsres, n2g, n2b, lnq1, lnq2, lns);
    gemm_s8<2><<<dim3(D4/BN, MT), 256, SMEM_GEMM>>>(lnq1, lnq2, lns, MP, q1_fc1, q2_fc1, s_fc1, fc1b, nullptr, bhid, M, D, D4);
    rowquant_kernel<<<M, 256>>>(bhid, hidq1, hidq2, hids, D4, MP, 1.f/127.f);
    gemm_s8<1><<<dim3(D/BN, MT), 256, SMEM_GEMM>>>(hidq1, hidq2, hids, MP, q1_fc2, q2_fc2, s_fc2, fc2b, bsres, out, M, D4, D);
}